// round 14
// baseline (speedup 1.0000x reference)
#include <cuda_runtime.h>
#include <math.h>
#include <float.h>

// layers: C = {64,128,256,512}, HW = {3136,784,196,49}, B=256, R=2000
#define NB 256
#define NR 2000
#define NRP 2048

__constant__ int c_C[4]    = {64, 128, 256, 512};
__constant__ int c_HW[4]   = {3136, 784, 196, 49};
__constant__ int c_qoff[4] = {0, 16384, 49152, 114688};

// scratch (static device globals; no allocation)
__device__ __align__(16) float g_fq[245760];        // pooled queries
__device__ __align__(16) float g_dot[4 * NB * NRP]; // q . ref^T, padded
__device__ float g_r2[4 * NR];
__device__ float g_q2[4 * NB];
__device__ float g_lid[NB * 4];

// ---- packed fp32x2 helpers (sm_103a FFMA2) ----
__device__ __forceinline__ unsigned long long pack2dup(float a) {
    unsigned long long r;
    asm("mov.b64 %0, {%1, %1};" : "=l"(r) : "f"(a));
    return r;
}
__device__ __forceinline__ void ffma2(unsigned long long& d,
                                      unsigned long long a,
                                      unsigned long long b) {
    asm("fma.rn.f32x2 %0, %1, %2, %0;" : "+l"(d) : "l"(a), "l"(b));
}
__device__ __forceinline__ void unpack2(float& lo, float& hi, unsigned long long v) {
    asm("mov.b64 {%0, %1}, %2;" : "=f"(lo), "=f"(hi) : "l"(v));
}

// ---------------- kernel 1: spatial mean pooling (proven) ----------------
__global__ void __launch_bounds__(256) pool_kernel(
    const float* __restrict__ f0, const float* __restrict__ f1,
    const float* __restrict__ f2, const float* __restrict__ f3)
{
    int gw   = (blockIdx.x * 256 + threadIdx.x) >> 5;
    int lane = threadIdx.x & 31;
    if (gw >= 245760) return;

    int l, base;
    if      (gw < 16384)  { l = 0; base = 0; }
    else if (gw < 49152)  { l = 1; base = 16384; }
    else if (gw < 114688) { l = 2; base = 49152; }
    else                  { l = 3; base = 114688; }
    int row = gw - base;
    const float* f = (l == 0) ? f0 : (l == 1) ? f1 : (l == 2) ? f2 : f3;
    int HW = c_HW[l];
    const float* src = f + (size_t)row * HW;

    float s = 0.f;
    if (l < 3) {
        const float4* s4 = (const float4*)src;
        int n4 = HW >> 2;
        #pragma unroll 4
        for (int i = lane; i < n4; i += 32) {
            float4 v = s4[i];
            s += (v.x + v.y) + (v.z + v.w);
        }
    } else {
        #pragma unroll 2
        for (int i = lane; i < HW; i += 32) s += src[i];
    }
    #pragma unroll
    for (int o = 16; o > 0; o >>= 1) s += __shfl_xor_sync(0xffffffffu, s, o);
    if (lane == 0) g_fq[c_qoff[l] + row] = s / (float)HW;
}

// ---------------- kernel 2: squared norms (proven) ----------------
__global__ void __launch_bounds__(256) norms_kernel(
    const float* __restrict__ r0, const float* __restrict__ r1,
    const float* __restrict__ r2, const float* __restrict__ r3)
{
    int gw   = (blockIdx.x * 256 + threadIdx.x) >> 5;
    int lane = threadIdx.x & 31;
    if (gw >= 9024) return;

    const float* src;
    float* out;
    int C;
    if (gw < 8000) {
        int l = gw / NR, row = gw % NR;
        const float* rp = (l == 0) ? r0 : (l == 1) ? r1 : (l == 2) ? r2 : r3;
        C = c_C[l];
        src = rp + (size_t)row * C;
        out = g_r2 + l * NR + row;
    } else {
        int idx = gw - 8000;
        int l = idx >> 8, row = idx & 255;
        C = c_C[l];
        src = g_fq + c_qoff[l] + (size_t)row * C;
        out = g_q2 + l * NB + row;
    }
    float s = 0.f;
    const float4* s4 = (const float4*)src;
    int n4 = C >> 2;
    #pragma unroll 4
    for (int i = lane; i < n4; i += 32) {
        float4 v = s4[i];
        s += v.x * v.x + v.y * v.y + v.z * v.z + v.w * v.w;
    }
    #pragma unroll
    for (int o = 16; o > 0; o >>= 1) s += __shfl_xor_sync(0xffffffffu, s, o);
    if (lane == 0) *out = s;
}

// ---------------- kernel 3: 128x64 tile, FFMA2 inner loop (proven R13) ----------------
__global__ void __launch_bounds__(256) dist_gemm_kernel(
    const float* __restrict__ r0, const float* __restrict__ r1,
    const float* __restrict__ r2, const float* __restrict__ r3)
{
    int l = 3 - blockIdx.z;
    int C = c_C[l];
    const float* ref = (l == 0) ? r0 : (l == 1) ? r1 : (l == 2) ? r2 : r3;
    const float* q   = g_fq + c_qoff[l];

    int bt = blockIdx.y << 7;
    int rt = blockIdx.x << 6;

    __shared__ __align__(16) float qs[2][16][132];
    __shared__ __align__(16) float rs[2][16][68];

    int tx = threadIdx.x;
    int ty = threadIdx.y;
    int tid = ty * 16 + tx;

    int isR  = tid >> 7;
    int qrow = tid & 127;
    int rrow = (tid & 127) >> 1;
    int rkg  = tid & 1;

    const float* gsrc;
    size_t gbase;
    int valid;
    if (isR) {
        int rr = rt + rrow;
        valid = (rr < NR);
        gbase = (size_t)(valid ? rr : 0) * C;
        gsrc  = ref;
    } else {
        valid = 1;
        gbase = (size_t)(bt + qrow) * C;
        gsrc  = q;
    }
    float* sq0 = &qs[0][0][0] + qrow;
    float* sq1 = &qs[1][0][0] + qrow;
    float* sr0 = &rs[0][0][0] + rrow;
    float* sr1 = &rs[1][0][0] + rrow;

    unsigned long long acc2[4][4];
    #pragma unroll
    for (int i = 0; i < 4; i++)
        #pragma unroll
        for (int j = 0; j < 4; j++) acc2[i][j] = 0ULL;

    if (!isR) {
        #pragma unroll
        for (int g = 0; g < 4; g++) {
            float4 v = *(const float4*)&gsrc[gbase + g * 4];
            sq0[(g * 4 + 0) * 132] = v.x;
            sq0[(g * 4 + 1) * 132] = v.y;
            sq0[(g * 4 + 2) * 132] = v.z;
            sq0[(g * 4 + 3) * 132] = v.w;
        }
    } else {
        #pragma unroll
        for (int g = 0; g < 2; g++) {
            float4 v = valid ? *(const float4*)&gsrc[gbase + rkg * 8 + g * 4]
                             : make_float4(0.f, 0.f, 0.f, 0.f);
            sr0[(rkg * 8 + g * 4 + 0) * 68] = v.x;
            sr0[(rkg * 8 + g * 4 + 1) * 68] = v.y;
            sr0[(rkg * 8 + g * 4 + 2) * 68] = v.z;
            sr0[(rkg * 8 + g * 4 + 3) * 68] = v.w;
        }
    }

    int nch = C >> 4;
    for (int ch = 0; ch < nch; ch++) {
        __syncthreads();
        int buf = ch & 1;

        float4 n0 = make_float4(0.f, 0.f, 0.f, 0.f);
        float4 n1 = make_float4(0.f, 0.f, 0.f, 0.f);
        float4 n2 = make_float4(0.f, 0.f, 0.f, 0.f);
        float4 n3 = make_float4(0.f, 0.f, 0.f, 0.f);
        if (ch + 1 < nch && valid) {
            size_t o = gbase + (size_t)(ch + 1) * 16;
            if (!isR) {
                n0 = *(const float4*)&gsrc[o];
                n1 = *(const float4*)&gsrc[o + 4];
                n2 = *(const float4*)&gsrc[o + 8];
                n3 = *(const float4*)&gsrc[o + 12];
            } else {
                n0 = *(const float4*)&gsrc[o + rkg * 8];
                n1 = *(const float4*)&gsrc[o + rkg * 8 + 4];
            }
        }

        #pragma unroll
        for (int kk = 0; kk < 16; kk++) {
            ulonglong2 qa = *(const ulonglong2*)&qs[buf][kk][ty * 8];
            ulonglong2 qb = *(const ulonglong2*)&qs[buf][kk][ty * 8 + 4];
            float4 rv = *(const float4*)&rs[buf][kk][tx * 4];
            unsigned long long rp0 = pack2dup(rv.x);
            unsigned long long rp1 = pack2dup(rv.y);
            unsigned long long rp2 = pack2dup(rv.z);
            unsigned long long rp3 = pack2dup(rv.w);
            ffma2(acc2[0][0], qa.x, rp0); ffma2(acc2[0][1], qa.x, rp1);
            ffma2(acc2[0][2], qa.x, rp2); ffma2(acc2[0][3], qa.x, rp3);
            ffma2(acc2[1][0], qa.y, rp0); ffma2(acc2[1][1], qa.y, rp1);
            ffma2(acc2[1][2], qa.y, rp2); ffma2(acc2[1][3], qa.y, rp3);
            ffma2(acc2[2][0], qb.x, rp0); ffma2(acc2[2][1], qb.x, rp1);
            ffma2(acc2[2][2], qb.x, rp2); ffma2(acc2[2][3], qb.x, rp3);
            ffma2(acc2[3][0], qb.y, rp0); ffma2(acc2[3][1], qb.y, rp1);
            ffma2(acc2[3][2], qb.y, rp2); ffma2(acc2[3][3], qb.y, rp3);
        }

        if (ch + 1 < nch) {
            if (!isR) {
                float* d = buf ? sq0 : sq1;
                d[0 * 132]  = n0.x; d[1 * 132]  = n0.y; d[2 * 132]  = n0.z; d[3 * 132]  = n0.w;
                d[4 * 132]  = n1.x; d[5 * 132]  = n1.y; d[6 * 132]  = n1.z; d[7 * 132]  = n1.w;
                d[8 * 132]  = n2.x; d[9 * 132]  = n2.y; d[10 * 132] = n2.z; d[11 * 132] = n2.w;
                d[12 * 132] = n3.x; d[13 * 132] = n3.y; d[14 * 132] = n3.z; d[15 * 132] = n3.w;
            } else {
                float* d = buf ? sr0 : sr1;
                d[(rkg * 8 + 0) * 68] = n0.x; d[(rkg * 8 + 1) * 68] = n0.y;
                d[(rkg * 8 + 2) * 68] = n0.z; d[(rkg * 8 + 3) * 68] = n0.w;
                d[(rkg * 8 + 4) * 68] = n1.x; d[(rkg * 8 + 5) * 68] = n1.y;
                d[(rkg * 8 + 6) * 68] = n1.z; d[(rkg * 8 + 7) * 68] = n1.w;
            }
        }
    }

    float* out = g_dot + ((size_t)l * NB + bt) * NRP + rt;
    #pragma unroll
    for (int p = 0; p < 4; p++) {
        float lo0, hi0, lo1, hi1, lo2, hi2, lo3, hi3;
        unpack2(lo0, hi0, acc2[p][0]);
        unpack2(lo1, hi1, acc2[p][1]);
        unpack2(lo2, hi2, acc2[p][2]);
        unpack2(lo3, hi3, acc2[p][3]);
        *(float4*)&out[(size_t)(ty * 8 + 2 * p) * NRP + tx * 4] =
            make_float4(lo0, lo1, lo2, lo3);
        *(float4*)&out[(size_t)(ty * 8 + 2 * p + 1) * NRP + tx * 4] =
            make_float4(hi0, hi1, hi2, hi3);
    }
}

// ---------------- kernel 4: warp-autonomous extraction (no per-round block barriers) ----------------
__global__ void __launch_bounds__(256) select_kernel(const int* __restrict__ kp)
{
    int b = blockIdx.x;
    int l = blockIdx.y;
    int tid  = threadIdx.x;
    int warp = tid >> 5;
    int lane = tid & 31;

    __shared__ unsigned candf[512];   // 8 warps x kp1 sorted candidates (flat)
    __shared__ float topd[64];

    const float* dotp = g_dot + ((size_t)l * NB + b) * NRP;
    const float* r2p  = g_r2 + l * NR;
    float q2v = g_q2[l * NB + b];

    int base = tid * 8;
    float4 d0 = *(const float4*)&dotp[base];
    float4 d1 = *(const float4*)&dotp[base + 4];
    float dd[8] = {d0.x, d0.y, d0.z, d0.w, d1.x, d1.y, d1.z, d1.w};
    unsigned u[8];
    #pragma unroll
    for (int j = 0; j < 8; j++) {
        int r = base + j;
        float x = (r < NR) ? fmaxf(q2v + r2p[r] - 2.f * dd[j], 0.f) : FLT_MAX;
        u[j] = __float_as_uint(x);   // nonneg: bit order == value order
    }

    int kk  = *kp;
    int kp1 = min(kk + 1, 64);

    // ---- phase A: each warp extracts its local top-kp1 (sorted), independently ----
    unsigned lm = min(min(min(u[0], u[1]), min(u[2], u[3])),
                      min(min(u[4], u[5]), min(u[6], u[7])));
    unsigned* myc = &candf[warp * kp1];
    for (int t = 0; t < kp1; t++) {
        unsigned wm = __reduce_min_sync(0xffffffffu, lm);
        if (lane == 0) myc[t] = wm;
        unsigned bal = __ballot_sync(0xffffffffu, lm == wm);
        if (lane == (__ffs(bal) - 1)) {
            bool done = false;
            #pragma unroll
            for (int j = 0; j < 8; j++)
                if (!done && u[j] == wm) { u[j] = 0xFFFFFFFFu; done = true; }
            lm = min(min(min(u[0], u[1]), min(u[2], u[3])),
                     min(min(u[4], u[5]), min(u[6], u[7])));
        }
    }
    __syncthreads();   // the only block barrier

    // ---- phase B: warp 0 extracts global top-kp1 from 8*kp1 candidates ----
    if (warp == 0) {
        int total = 8 * kp1;   // <= 512 = 32*16
        unsigned v[16];
        #pragma unroll
        for (int j = 0; j < 16; j++) {
            int idx = lane + 32 * j;
            v[j] = (idx < total) ? candf[idx] : 0xFFFFFFFFu;
        }
        unsigned lm2 = v[0];
        #pragma unroll
        for (int j = 1; j < 16; j++) lm2 = min(lm2, v[j]);

        for (int t = 0; t < kp1; t++) {
            unsigned wm = __reduce_min_sync(0xffffffffu, lm2);
            if (lane == 0) topd[t] = __uint_as_float(wm);
            unsigned bal = __ballot_sync(0xffffffffu, lm2 == wm);
            if (lane == (__ffs(bal) - 1)) {
                bool done = false;
                #pragma unroll
                for (int j = 0; j < 16; j++)
                    if (!done && v[j] == wm) { v[j] = 0xFFFFFFFFu; done = true; }
                lm2 = v[0];
                #pragma unroll
                for (int j = 1; j < 16; j++) lm2 = min(lm2, v[j]);
            }
        }
        __syncwarp();

        // LID: drop nearest (topd[0]); d_i = sqrt(topd[i]), d_k = sqrt(topd[kp1-1])
        float dk = sqrtf(topd[kp1 - 1]);
        float s = 0.f;
        for (int i = lane; i < kp1; i += 32)
            if (i >= 1) s += logf(sqrtf(topd[i]) / dk);
        #pragma unroll
        for (int o = 16; o > 0; o >>= 1) s += __shfl_xor_sync(0xffffffffu, s, o);
        if (lane == 0) g_lid[b * 4 + l] = -(float)kk / s;
    }
}

// ---------------- kernel 5: linear head + sigmoid ----------------
__global__ void final_kernel(const float* __restrict__ w,
                             const float* __restrict__ bb,
                             float* __restrict__ out)
{
    int b = threadIdx.x;
    float z = bb[0];
    #pragma unroll
    for (int j = 0; j < 4; j++) z += g_lid[b * 4 + j] * w[j];
    out[b] = 1.f / (1.f + expf(-z));
}

// ---------------- launch (single stream, proven order) ----------------
extern "C" void kernel_launch(void* const* d_in, const int* in_sizes, int n_in,
                              void* d_out, int out_size)
{
    const float* feat[4] = {0, 0, 0, 0};
    const float* ref[4]  = {0, 0, 0, 0};
    const float* rw = 0;
    const float* rb = 0;
    const int*   kp = 0;
    int ones = 0;
    for (int i = 0; i < n_in; i++) {
        switch (in_sizes[i]) {
            case 51380224: feat[0] = (const float*)d_in[i]; break;
            case 25690112: feat[1] = (const float*)d_in[i]; break;
            case 12845056: feat[2] = (const float*)d_in[i]; break;
            case 6422528:  feat[3] = (const float*)d_in[i]; break;
            case 128000:   ref[0]  = (const float*)d_in[i]; break;
            case 256000:   ref[1]  = (const float*)d_in[i]; break;
            case 512000:   ref[2]  = (const float*)d_in[i]; break;
            case 1024000:  ref[3]  = (const float*)d_in[i]; break;
            case 4:        rw      = (const float*)d_in[i]; break;
            case 1:
                if (ones++ == 0) rb = (const float*)d_in[i];
                else             kp = (const int*)d_in[i];
                break;
            default: break;
        }
    }

    pool_kernel<<<30720, 256>>>(feat[0], feat[1], feat[2], feat[3]);
    norms_kernel<<<1128, 256>>>(ref[0], ref[1], ref[2], ref[3]);

    dim3 gg(NRP / 64, NB / 128, 4);
    dim3 bt(16, 16);
    dist_gemm_kernel<<<gg, bt>>>(ref[0], ref[1], ref[2], ref[3]);

    dim3 gs(NB, 4);
    select_kernel<<<gs, 256>>>(kp);

    final_kernel<<<1, 256>>>(rw, rb, (float*)d_out);
}

// round 15
// speedup vs baseline: 1.0325x; 1.0325x over previous
#include <cuda_runtime.h>
#include <math.h>
#include <float.h>

// layers: C = {64,128,256,512}, HW = {3136,784,196,49}, B=256, R=2000
#define NB 256
#define NR 2000
#define NRP 2048

__constant__ int c_C[4]    = {64, 128, 256, 512};
__constant__ int c_HW[4]   = {3136, 784, 196, 49};
__constant__ int c_qoff[4] = {0, 16384, 49152, 114688};

// scratch (static device globals; no allocation)
__device__ __align__(16) float g_fq[245760];        // pooled queries
__device__ __align__(16) float g_dot[4 * NB * NRP]; // q . ref^T, padded
__device__ float g_r2[4 * NR];
__device__ float g_lid[NB * 4];
__device__ unsigned g_ctr;                          // last-block ticket (reset each call)

// ---- packed fp32x2 helpers (sm_103a FFMA2) ----
__device__ __forceinline__ unsigned long long pack2dup(float a) {
    unsigned long long r;
    asm("mov.b64 %0, {%1, %1};" : "=l"(r) : "f"(a));
    return r;
}
__device__ __forceinline__ void ffma2(unsigned long long& d,
                                      unsigned long long a,
                                      unsigned long long b) {
    asm("fma.rn.f32x2 %0, %1, %2, %0;" : "+l"(d) : "l"(a), "l"(b));
}
__device__ __forceinline__ void unpack2(float& lo, float& hi, unsigned long long v) {
    asm("mov.b64 {%0, %1}, %2;" : "=f"(lo), "=f"(hi) : "l"(v));
}

// ---------------- kernel 1: pooling + ref norms fused ----------------
__global__ void __launch_bounds__(256) pool_norm_kernel(
    const float* __restrict__ f0, const float* __restrict__ f1,
    const float* __restrict__ f2, const float* __restrict__ f3,
    const float* __restrict__ r0, const float* __restrict__ r1,
    const float* __restrict__ r2, const float* __restrict__ r3)
{
    int lane = threadIdx.x & 31;

    if (blockIdx.x < 30720) {
        // ---- pooling: warp per (b,c) row ----
        int gw = (blockIdx.x * 256 + threadIdx.x) >> 5;
        int l, base;
        if      (gw < 16384)  { l = 0; base = 0; }
        else if (gw < 49152)  { l = 1; base = 16384; }
        else if (gw < 114688) { l = 2; base = 49152; }
        else                  { l = 3; base = 114688; }
        int row = gw - base;
        const float* f = (l == 0) ? f0 : (l == 1) ? f1 : (l == 2) ? f2 : f3;
        int HW = c_HW[l];
        const float* src = f + (size_t)row * HW;

        float s = 0.f;
        if (l < 3) {
            const float4* s4 = (const float4*)src;
            int n4 = HW >> 2;
            #pragma unroll 4
            for (int i = lane; i < n4; i += 32) {
                float4 v = s4[i];
                s += (v.x + v.y) + (v.z + v.w);
            }
        } else {
            #pragma unroll 2
            for (int i = lane; i < HW; i += 32) s += src[i];
        }
        #pragma unroll
        for (int o = 16; o > 0; o >>= 1) s += __shfl_xor_sync(0xffffffffu, s, o);
        if (lane == 0) g_fq[c_qoff[l] + row] = s / (float)HW;
    } else {
        // ---- ref norms: warp per ref row (8000 rows over 1000 blocks) ----
        int gw = ((blockIdx.x - 30720) * 256 + threadIdx.x) >> 5;
        int l = gw / NR, row = gw % NR;
        const float* rp = (l == 0) ? r0 : (l == 1) ? r1 : (l == 2) ? r2 : r3;
        int C = c_C[l];
        const float* src = rp + (size_t)row * C;
        float s = 0.f;
        const float4* s4 = (const float4*)src;
        int n4 = C >> 2;
        #pragma unroll 4
        for (int i = lane; i < n4; i += 32) {
            float4 v = s4[i];
            s += v.x * v.x + v.y * v.y + v.z * v.z + v.w * v.w;
        }
        #pragma unroll
        for (int o = 16; o > 0; o >>= 1) s += __shfl_xor_sync(0xffffffffu, s, o);
        if (lane == 0) g_r2[l * NR + row] = s;
    }
}

// ---------------- kernel 2: 128x64 tile, FFMA2 inner loop (proven R13) ----------------
__global__ void __launch_bounds__(256) dist_gemm_kernel(
    const float* __restrict__ r0, const float* __restrict__ r1,
    const float* __restrict__ r2, const float* __restrict__ r3)
{
    int l = 3 - blockIdx.z;
    int C = c_C[l];
    const float* ref = (l == 0) ? r0 : (l == 1) ? r1 : (l == 2) ? r2 : r3;
    const float* q   = g_fq + c_qoff[l];

    int bt = blockIdx.y << 7;
    int rt = blockIdx.x << 6;

    __shared__ __align__(16) float qs[2][16][132];
    __shared__ __align__(16) float rs[2][16][68];

    int tx = threadIdx.x;
    int ty = threadIdx.y;
    int tid = ty * 16 + tx;

    int isR  = tid >> 7;
    int qrow = tid & 127;
    int rrow = (tid & 127) >> 1;
    int rkg  = tid & 1;

    const float* gsrc;
    size_t gbase;
    int valid;
    if (isR) {
        int rr = rt + rrow;
        valid = (rr < NR);
        gbase = (size_t)(valid ? rr : 0) * C;
        gsrc  = ref;
    } else {
        valid = 1;
        gbase = (size_t)(bt + qrow) * C;
        gsrc  = q;
    }
    float* sq0 = &qs[0][0][0] + qrow;
    float* sq1 = &qs[1][0][0] + qrow;
    float* sr0 = &rs[0][0][0] + rrow;
    float* sr1 = &rs[1][0][0] + rrow;

    unsigned long long acc2[4][4];
    #pragma unroll
    for (int i = 0; i < 4; i++)
        #pragma unroll
        for (int j = 0; j < 4; j++) acc2[i][j] = 0ULL;

    if (!isR) {
        #pragma unroll
        for (int g = 0; g < 4; g++) {
            float4 v = *(const float4*)&gsrc[gbase + g * 4];
            sq0[(g * 4 + 0) * 132] = v.x;
            sq0[(g * 4 + 1) * 132] = v.y;
            sq0[(g * 4 + 2) * 132] = v.z;
            sq0[(g * 4 + 3) * 132] = v.w;
        }
    } else {
        #pragma unroll
        for (int g = 0; g < 2; g++) {
            float4 v = valid ? *(const float4*)&gsrc[gbase + rkg * 8 + g * 4]
                             : make_float4(0.f, 0.f, 0.f, 0.f);
            sr0[(rkg * 8 + g * 4 + 0) * 68] = v.x;
            sr0[(rkg * 8 + g * 4 + 1) * 68] = v.y;
            sr0[(rkg * 8 + g * 4 + 2) * 68] = v.z;
            sr0[(rkg * 8 + g * 4 + 3) * 68] = v.w;
        }
    }

    int nch = C >> 4;
    for (int ch = 0; ch < nch; ch++) {
        __syncthreads();
        int buf = ch & 1;

        float4 n0 = make_float4(0.f, 0.f, 0.f, 0.f);
        float4 n1 = make_float4(0.f, 0.f, 0.f, 0.f);
        float4 n2 = make_float4(0.f, 0.f, 0.f, 0.f);
        float4 n3 = make_float4(0.f, 0.f, 0.f, 0.f);
        if (ch + 1 < nch && valid) {
            size_t o = gbase + (size_t)(ch + 1) * 16;
            if (!isR) {
                n0 = *(const float4*)&gsrc[o];
                n1 = *(const float4*)&gsrc[o + 4];
                n2 = *(const float4*)&gsrc[o + 8];
                n3 = *(const float4*)&gsrc[o + 12];
            } else {
                n0 = *(const float4*)&gsrc[o + rkg * 8];
                n1 = *(const float4*)&gsrc[o + rkg * 8 + 4];
            }
        }

        #pragma unroll
        for (int kk = 0; kk < 16; kk++) {
            ulonglong2 qa = *(const ulonglong2*)&qs[buf][kk][ty * 8];
            ulonglong2 qb = *(const ulonglong2*)&qs[buf][kk][ty * 8 + 4];
            float4 rv = *(const float4*)&rs[buf][kk][tx * 4];
            unsigned long long rp0 = pack2dup(rv.x);
            unsigned long long rp1 = pack2dup(rv.y);
            unsigned long long rp2 = pack2dup(rv.z);
            unsigned long long rp3 = pack2dup(rv.w);
            ffma2(acc2[0][0], qa.x, rp0); ffma2(acc2[0][1], qa.x, rp1);
            ffma2(acc2[0][2], qa.x, rp2); ffma2(acc2[0][3], qa.x, rp3);
            ffma2(acc2[1][0], qa.y, rp0); ffma2(acc2[1][1], qa.y, rp1);
            ffma2(acc2[1][2], qa.y, rp2); ffma2(acc2[1][3], qa.y, rp3);
            ffma2(acc2[2][0], qb.x, rp0); ffma2(acc2[2][1], qb.x, rp1);
            ffma2(acc2[2][2], qb.x, rp2); ffma2(acc2[2][3], qb.x, rp3);
            ffma2(acc2[3][0], qb.y, rp0); ffma2(acc2[3][1], qb.y, rp1);
            ffma2(acc2[3][2], qb.y, rp2); ffma2(acc2[3][3], qb.y, rp3);
        }

        if (ch + 1 < nch) {
            if (!isR) {
                float* d = buf ? sq0 : sq1;
                d[0 * 132]  = n0.x; d[1 * 132]  = n0.y; d[2 * 132]  = n0.z; d[3 * 132]  = n0.w;
                d[4 * 132]  = n1.x; d[5 * 132]  = n1.y; d[6 * 132]  = n1.z; d[7 * 132]  = n1.w;
                d[8 * 132]  = n2.x; d[9 * 132]  = n2.y; d[10 * 132] = n2.z; d[11 * 132] = n2.w;
                d[12 * 132] = n3.x; d[13 * 132] = n3.y; d[14 * 132] = n3.z; d[15 * 132] = n3.w;
            } else {
                float* d = buf ? sr0 : sr1;
                d[(rkg * 8 + 0) * 68] = n0.x; d[(rkg * 8 + 1) * 68] = n0.y;
                d[(rkg * 8 + 2) * 68] = n0.z; d[(rkg * 8 + 3) * 68] = n0.w;
                d[(rkg * 8 + 4) * 68] = n1.x; d[(rkg * 8 + 5) * 68] = n1.y;
                d[(rkg * 8 + 6) * 68] = n1.z; d[(rkg * 8 + 7) * 68] = n1.w;
            }
        }
    }

    float* out = g_dot + ((size_t)l * NB + bt) * NRP + rt;
    #pragma unroll
    for (int p = 0; p < 4; p++) {
        float lo0, hi0, lo1, hi1, lo2, hi2, lo3, hi3;
        unpack2(lo0, hi0, acc2[p][0]);
        unpack2(lo1, hi1, acc2[p][1]);
        unpack2(lo2, hi2, acc2[p][2]);
        unpack2(lo3, hi3, acc2[p][3]);
        *(float4*)&out[(size_t)(ty * 8 + 2 * p) * NRP + tx * 4] =
            make_float4(lo0, lo1, lo2, lo3);
        *(float4*)&out[(size_t)(ty * 8 + 2 * p + 1) * NRP + tx * 4] =
            make_float4(hi0, hi1, hi2, hi3);
    }
}

// ---------------- kernel 3: R8 extraction select + inline q2 + fused final ----------------
__global__ void __launch_bounds__(256) select_kernel(
    const int* __restrict__ kp, const float* __restrict__ rw,
    const float* __restrict__ rb, float* __restrict__ outp)
{
    int b = blockIdx.x;
    int l = blockIdx.y;
    int tid  = threadIdx.x;
    int warp = tid >> 5;
    int lane = tid & 31;

    __shared__ unsigned wv[2][8];
    __shared__ float wq[8];
    __shared__ float topd[64];
    __shared__ int slast;

    int C = c_C[l];
    const float* dotp = g_dot + ((size_t)l * NB + b) * NRP;
    const float* r2p  = g_r2 + l * NR;

    // ---- inline q2 = ||fq[b]||^2 (replaces norms_kernel's q-part) ----
    const float* qrow = g_fq + c_qoff[l] + (size_t)b * C;
    float sq = 0.f;
    int n4 = C >> 2;
    if (tid < n4) {
        float4 v = ((const float4*)qrow)[tid];
        sq = v.x * v.x + v.y * v.y + v.z * v.z + v.w * v.w;
    }
    #pragma unroll
    for (int o = 16; o > 0; o >>= 1) sq += __shfl_xor_sync(0xffffffffu, sq, o);
    if (lane == 0) wq[warp] = sq;
    __syncthreads();
    float q2v = wq[0] + wq[1] + wq[2] + wq[3] + wq[4] + wq[5] + wq[6] + wq[7];

    // ---- distances in registers (bit-ordered uints) ----
    int base = tid * 8;
    float4 d0 = *(const float4*)&dotp[base];
    float4 d1 = *(const float4*)&dotp[base + 4];
    float dd[8] = {d0.x, d0.y, d0.z, d0.w, d1.x, d1.y, d1.z, d1.w};
    unsigned u[8];
    #pragma unroll
    for (int j = 0; j < 8; j++) {
        int r = base + j;
        float x = (r < NR) ? fmaxf(q2v + r2p[r] - 2.f * dd[j], 0.f) : FLT_MAX;
        u[j] = __float_as_uint(x);
    }

    int kk  = *kp;
    int kp1 = min(kk + 1, 64);

    // ---- R8 extraction rounds (proven) ----
    for (int t = 0; t < kp1; t++) {
        unsigned a0 = min(u[0], u[1]), a1 = min(u[2], u[3]);
        unsigned a2 = min(u[4], u[5]), a3 = min(u[6], u[7]);
        unsigned lm = min(min(a0, a1), min(a2, a3));
        unsigned wm = __reduce_min_sync(0xffffffffu, lm);
        unsigned bal = __ballot_sync(0xffffffffu, lm == wm);
        bool leader = (lane == (__ffs(bal) - 1));
        int p = t & 1;
        if (lane == 0) wv[p][warp] = wm;
        __syncthreads();
        unsigned bm = wv[p][0]; int bw = 0;
        #pragma unroll
        for (int w = 1; w < 8; w++) {
            unsigned x = wv[p][w];
            if (x < bm) { bm = x; bw = w; }
        }
        if (tid == 0) topd[t] = __uint_as_float(bm);
        if (warp == bw && leader) {
            bool done = false;
            #pragma unroll
            for (int j = 0; j < 8; j++)
                if (!done && u[j] == wm) { u[j] = 0xFFFFFFFFu; done = true; }
        }
    }
    __syncthreads();

    // ---- LID ----
    if (warp == 0) {
        float dk = sqrtf(topd[kp1 - 1]);
        float s = 0.f;
        for (int i = lane; i < kp1; i += 32)
            if (i >= 1) s += logf(sqrtf(topd[i]) / dk);
        #pragma unroll
        for (int o = 16; o > 0; o >>= 1) s += __shfl_xor_sync(0xffffffffu, s, o);
        if (lane == 0) g_lid[b * 4 + l] = -(float)kk / s;
    }

    // ---- fused final: last block computes the sigmoid head ----
    if (tid == 0) {
        __threadfence();
        unsigned t = atomicAdd(&g_ctr, 1u);
        slast = (t == (unsigned)(NB * 4 - 1));
    }
    __syncthreads();
    if (slast) {
        __threadfence();
        float z = rb[0];
        #pragma unroll
        for (int j = 0; j < 4; j++) z += g_lid[tid * 4 + j] * rw[j];
        outp[tid] = 1.f / (1.f + expf(-z));
        if (tid == 0) atomicExch(&g_ctr, 0u);   // reset for next graph replay
    }
}

// ---------------- launch (3 kernels) ----------------
extern "C" void kernel_launch(void* const* d_in, const int* in_sizes, int n_in,
                              void* d_out, int out_size)
{
    const float* feat[4] = {0, 0, 0, 0};
    const float* ref[4]  = {0, 0, 0, 0};
    const float* rw = 0;
    const float* rb = 0;
    const int*   kp = 0;
    int ones = 0;
    for (int i = 0; i < n_in; i++) {
        switch (in_sizes[i]) {
            case 51380224: feat[0] = (const float*)d_in[i]; break;
            case 25690112: feat[1] = (const float*)d_in[i]; break;
            case 12845056: feat[2] = (const float*)d_in[i]; break;
            case 6422528:  feat[3] = (const float*)d_in[i]; break;
            case 128000:   ref[0]  = (const float*)d_in[i]; break;
            case 256000:   ref[1]  = (const float*)d_in[i]; break;
            case 512000:   ref[2]  = (const float*)d_in[i]; break;
            case 1024000:  ref[3]  = (const float*)d_in[i]; break;
            case 4:        rw      = (const float*)d_in[i]; break;
            case 1:
                if (ones++ == 0) rb = (const float*)d_in[i];
                else             kp = (const int*)d_in[i];
                break;
            default: break;
        }
    }

    pool_norm_kernel<<<31720, 256>>>(feat[0], feat[1], feat[2], feat[3],
                                     ref[0], ref[1], ref[2], ref[3]);

    dim3 gg(NRP / 64, NB / 128, 4);
    dim3 bt(16, 16);
    dist_gemm_kernel<<<gg, bt>>>(ref[0], ref[1], ref[2], ref[3]);

    dim3 gs(NB, 4);
    select_kernel<<<gs, 256>>>(kp, rw, rb, (float*)d_out);
}

// round 16
// speedup vs baseline: 1.1433x; 1.1074x over previous
#include <cuda_runtime.h>
#include <math.h>
#include <float.h>

// layers: C = {64,128,256,512}, HW = {3136,784,196,49}, B=256, R=2000
#define NB 256
#define NR 2000
#define NRP 2048

__constant__ int c_C[4]    = {64, 128, 256, 512};
__constant__ int c_qoff[4] = {0, 16384, 49152, 114688};

// scratch (static device globals; no allocation)
__device__ __align__(16) float g_fq[245760];        // pooled queries
__device__ __align__(16) float g_dot[4 * NB * NRP]; // q . ref^T, padded
__device__ float g_r2[4 * NR];
__device__ float g_lid[NB * 4];
__device__ unsigned g_ctr;                          // last-block ticket (reset each call)

// ---- packed fp32x2 helpers (sm_103a FFMA2) ----
__device__ __forceinline__ unsigned long long pack2dup(float a) {
    unsigned long long r;
    asm("mov.b64 %0, {%1, %1};" : "=l"(r) : "f"(a));
    return r;
}
__device__ __forceinline__ void ffma2(unsigned long long& d,
                                      unsigned long long a,
                                      unsigned long long b) {
    asm("fma.rn.f32x2 %0, %1, %2, %0;" : "+l"(d) : "l"(a), "l"(b));
}
__device__ __forceinline__ void unpack2(float& lo, float& hi, unsigned long long v) {
    asm("mov.b64 {%0, %1}, %2;" : "=f"(lo), "=f"(hi) : "l"(v));
}

// ---------------- kernel 1: pooling (sub-warp rows for short layers) + ref norms ----------------
// warp map: [0,16384) L0 1row/warp | [16384,49152) L1 1row/warp |
//           [49152,81920) L2 2rows/warp | [81920,114688) L3 4rows/warp |
//           [114688,122688) ref norms 1row/warp
__global__ void __launch_bounds__(256) pool_norm_kernel(
    const float* __restrict__ f0, const float* __restrict__ f1,
    const float* __restrict__ f2, const float* __restrict__ f3,
    const float* __restrict__ r0, const float* __restrict__ r1,
    const float* __restrict__ r2, const float* __restrict__ r3)
{
    int gw   = (blockIdx.x * 256 + threadIdx.x) >> 5;
    int lane = threadIdx.x & 31;
    if (gw >= 122688) return;

    if (gw < 16384) {
        // L0: HW=3136, one row per warp, float4
        const float* src = f0 + (size_t)gw * 3136;
        const float4* s4 = (const float4*)src;
        float s = 0.f;
        #pragma unroll 4
        for (int i = lane; i < 784; i += 32) {
            float4 v = s4[i];
            s += (v.x + v.y) + (v.z + v.w);
        }
        #pragma unroll
        for (int o = 16; o > 0; o >>= 1) s += __shfl_xor_sync(0xffffffffu, s, o);
        if (lane == 0) g_fq[gw] = s / 3136.f;
    } else if (gw < 49152) {
        // L1: HW=784, one row per warp, float4
        int row = gw - 16384;
        const float* src = f1 + (size_t)row * 784;
        const float4* s4 = (const float4*)src;
        float s = 0.f;
        #pragma unroll 4
        for (int i = lane; i < 196; i += 32) {
            float4 v = s4[i];
            s += (v.x + v.y) + (v.z + v.w);
        }
        #pragma unroll
        for (int o = 16; o > 0; o >>= 1) s += __shfl_xor_sync(0xffffffffu, s, o);
        if (lane == 0) g_fq[16384 + row] = s / 784.f;
    } else if (gw < 81920) {
        // L2: HW=196, TWO rows per warp, 16 lanes per row, float4 (49 per row)
        int base = (gw - 49152) * 2;
        int g    = lane >> 4;        // 0/1 -> which row
        int sub  = lane & 15;
        int row  = base + g;
        const float4* s4 = (const float4*)(f2 + (size_t)row * 196);
        float s = 0.f;
        #pragma unroll 4
        for (int i = sub; i < 49; i += 16) {
            float4 v = s4[i];
            s += (v.x + v.y) + (v.z + v.w);
        }
        #pragma unroll
        for (int o = 8; o > 0; o >>= 1) s += __shfl_xor_sync(0xffffffffu, s, o);
        if (sub == 0) g_fq[49152 + row] = s / 196.f;
    } else if (gw < 114688) {
        // L3: HW=49, FOUR rows per warp, 8 lanes per row, scalar
        int base = (gw - 81920) * 4;
        int g    = lane >> 3;        // 0..3 -> which row
        int sub  = lane & 7;
        int row  = base + g;
        const float* src = f3 + (size_t)row * 49;
        float s = 0.f;
        #pragma unroll 7
        for (int i = sub; i < 49; i += 8) s += src[i];
        #pragma unroll
        for (int o = 4; o > 0; o >>= 1) s += __shfl_xor_sync(0xffffffffu, s, o);
        if (sub == 0) g_fq[114688 + row] = s / 49.f;
    } else {
        // ref norms: warp per ref row
        int idx = gw - 114688;       // 0..7999
        int l = idx / NR, row = idx % NR;
        const float* rp = (l == 0) ? r0 : (l == 1) ? r1 : (l == 2) ? r2 : r3;
        int C = c_C[l];
        const float* src = rp + (size_t)row * C;
        float s = 0.f;
        const float4* s4 = (const float4*)src;
        int n4 = C >> 2;
        #pragma unroll 4
        for (int i = lane; i < n4; i += 32) {
            float4 v = s4[i];
            s += v.x * v.x + v.y * v.y + v.z * v.z + v.w * v.w;
        }
        #pragma unroll
        for (int o = 16; o > 0; o >>= 1) s += __shfl_xor_sync(0xffffffffu, s, o);
        if (lane == 0) g_r2[l * NR + row] = s;
    }
}

// ---------------- kernel 2: 128x64 tile, FFMA2 inner loop (proven R13) ----------------
__global__ void __launch_bounds__(256) dist_gemm_kernel(
    const float* __restrict__ r0, const float* __restrict__ r1,
    const float* __restrict__ r2, const float* __restrict__ r3)
{
    int l = 3 - blockIdx.z;
    int C = c_C[l];
    const float* ref = (l == 0) ? r0 : (l == 1) ? r1 : (l == 2) ? r2 : r3;
    const float* q   = g_fq + c_qoff[l];

    int bt = blockIdx.y << 7;
    int rt = blockIdx.x << 6;

    __shared__ __align__(16) float qs[2][16][132];
    __shared__ __align__(16) float rs[2][16][68];

    int tx = threadIdx.x;
    int ty = threadIdx.y;
    int tid = ty * 16 + tx;

    int isR  = tid >> 7;
    int qrow = tid & 127;
    int rrow = (tid & 127) >> 1;
    int rkg  = tid & 1;

    const float* gsrc;
    size_t gbase;
    int valid;
    if (isR) {
        int rr = rt + rrow;
        valid = (rr < NR);
        gbase = (size_t)(valid ? rr : 0) * C;
        gsrc  = ref;
    } else {
        valid = 1;
        gbase = (size_t)(bt + qrow) * C;
        gsrc  = q;
    }
    float* sq0 = &qs[0][0][0] + qrow;
    float* sq1 = &qs[1][0][0] + qrow;
    float* sr0 = &rs[0][0][0] + rrow;
    float* sr1 = &rs[1][0][0] + rrow;

    unsigned long long acc2[4][4];
    #pragma unroll
    for (int i = 0; i < 4; i++)
        #pragma unroll
        for (int j = 0; j < 4; j++) acc2[i][j] = 0ULL;

    if (!isR) {
        #pragma unroll
        for (int g = 0; g < 4; g++) {
            float4 v = *(const float4*)&gsrc[gbase + g * 4];
            sq0[(g * 4 + 0) * 132] = v.x;
            sq0[(g * 4 + 1) * 132] = v.y;
            sq0[(g * 4 + 2) * 132] = v.z;
            sq0[(g * 4 + 3) * 132] = v.w;
        }
    } else {
        #pragma unroll
        for (int g = 0; g < 2; g++) {
            float4 v = valid ? *(const float4*)&gsrc[gbase + rkg * 8 + g * 4]
                             : make_float4(0.f, 0.f, 0.f, 0.f);
            sr0[(rkg * 8 + g * 4 + 0) * 68] = v.x;
            sr0[(rkg * 8 + g * 4 + 1) * 68] = v.y;
            sr0[(rkg * 8 + g * 4 + 2) * 68] = v.z;
            sr0[(rkg * 8 + g * 4 + 3) * 68] = v.w;
        }
    }

    int nch = C >> 4;
    for (int ch = 0; ch < nch; ch++) {
        __syncthreads();
        int buf = ch & 1;

        float4 n0 = make_float4(0.f, 0.f, 0.f, 0.f);
        float4 n1 = make_float4(0.f, 0.f, 0.f, 0.f);
        float4 n2 = make_float4(0.f, 0.f, 0.f, 0.f);
        float4 n3 = make_float4(0.f, 0.f, 0.f, 0.f);
        if (ch + 1 < nch && valid) {
            size_t o = gbase + (size_t)(ch + 1) * 16;
            if (!isR) {
                n0 = *(const float4*)&gsrc[o];
                n1 = *(const float4*)&gsrc[o + 4];
                n2 = *(const float4*)&gsrc[o + 8];
                n3 = *(const float4*)&gsrc[o + 12];
            } else {
                n0 = *(const float4*)&gsrc[o + rkg * 8];
                n1 = *(const float4*)&gsrc[o + rkg * 8 + 4];
            }
        }

        #pragma unroll
        for (int kk = 0; kk < 16; kk++) {
            ulonglong2 qa = *(const ulonglong2*)&qs[buf][kk][ty * 8];
            ulonglong2 qb = *(const ulonglong2*)&qs[buf][kk][ty * 8 + 4];
            float4 rv = *(const float4*)&rs[buf][kk][tx * 4];
            unsigned long long rp0 = pack2dup(rv.x);
            unsigned long long rp1 = pack2dup(rv.y);
            unsigned long long rp2 = pack2dup(rv.z);
            unsigned long long rp3 = pack2dup(rv.w);
            ffma2(acc2[0][0], qa.x, rp0); ffma2(acc2[0][1], qa.x, rp1);
            ffma2(acc2[0][2], qa.x, rp2); ffma2(acc2[0][3], qa.x, rp3);
            ffma2(acc2[1][0], qa.y, rp0); ffma2(acc2[1][1], qa.y, rp1);
            ffma2(acc2[1][2], qa.y, rp2); ffma2(acc2[1][3], qa.y, rp3);
            ffma2(acc2[2][0], qb.x, rp0); ffma2(acc2[2][1], qb.x, rp1);
            ffma2(acc2[2][2], qb.x, rp2); ffma2(acc2[2][3], qb.x, rp3);
            ffma2(acc2[3][0], qb.y, rp0); ffma2(acc2[3][1], qb.y, rp1);
            ffma2(acc2[3][2], qb.y, rp2); ffma2(acc2[3][3], qb.y, rp3);
        }

        if (ch + 1 < nch) {
            if (!isR) {
                float* d = buf ? sq0 : sq1;
                d[0 * 132]  = n0.x; d[1 * 132]  = n0.y; d[2 * 132]  = n0.z; d[3 * 132]  = n0.w;
                d[4 * 132]  = n1.x; d[5 * 132]  = n1.y; d[6 * 132]  = n1.z; d[7 * 132]  = n1.w;
                d[8 * 132]  = n2.x; d[9 * 132]  = n2.y; d[10 * 132] = n2.z; d[11 * 132] = n2.w;
                d[12 * 132] = n3.x; d[13 * 132] = n3.y; d[14 * 132] = n3.z; d[15 * 132] = n3.w;
            } else {
                float* d = buf ? sr0 : sr1;
                d[(rkg * 8 + 0) * 68] = n0.x; d[(rkg * 8 + 1) * 68] = n0.y;
                d[(rkg * 8 + 2) * 68] = n0.z; d[(rkg * 8 + 3) * 68] = n0.w;
                d[(rkg * 8 + 4) * 68] = n1.x; d[(rkg * 8 + 5) * 68] = n1.y;
                d[(rkg * 8 + 6) * 68] = n1.z; d[(rkg * 8 + 7) * 68] = n1.w;
            }
        }
    }

    float* out = g_dot + ((size_t)l * NB + bt) * NRP + rt;
    #pragma unroll
    for (int p = 0; p < 4; p++) {
        float lo0, hi0, lo1, hi1, lo2, hi2, lo3, hi3;
        unpack2(lo0, hi0, acc2[p][0]);
        unpack2(lo1, hi1, acc2[p][1]);
        unpack2(lo2, hi2, acc2[p][2]);
        unpack2(lo3, hi3, acc2[p][3]);
        *(float4*)&out[(size_t)(ty * 8 + 2 * p) * NRP + tx * 4] =
            make_float4(lo0, lo1, lo2, lo3);
        *(float4*)&out[(size_t)(ty * 8 + 2 * p + 1) * NRP + tx * 4] =
            make_float4(hi0, hi1, hi2, hi3);
    }
}

// ---------------- kernel 3: R8 extraction select + inline q2 + fused final (proven R15) ----------------
__global__ void __launch_bounds__(256) select_kernel(
    const int* __restrict__ kp, const float* __restrict__ rw,
    const float* __restrict__ rb, float* __restrict__ outp)
{
    int b = blockIdx.x;
    int l = blockIdx.y;
    int tid  = threadIdx.x;
    int warp = tid >> 5;
    int lane = tid & 31;

    __shared__ unsigned wv[2][8];
    __shared__ float wq[8];
    __shared__ float topd[64];
    __shared__ int slast;

    int C = c_C[l];
    const float* dotp = g_dot + ((size_t)l * NB + b) * NRP;
    const float* r2p  = g_r2 + l * NR;

    // inline q2 = ||fq[b]||^2
    const float* qrow = g_fq + c_qoff[l] + (size_t)b * C;
    float sq = 0.f;
    int n4 = C >> 2;
    if (tid < n4) {
        float4 v = ((const float4*)qrow)[tid];
        sq = v.x * v.x + v.y * v.y + v.z * v.z + v.w * v.w;
    }
    #pragma unroll
    for (int o = 16; o > 0; o >>= 1) sq += __shfl_xor_sync(0xffffffffu, sq, o);
    if (lane == 0) wq[warp] = sq;
    __syncthreads();
    float q2v = wq[0] + wq[1] + wq[2] + wq[3] + wq[4] + wq[5] + wq[6] + wq[7];

    int base = tid * 8;
    float4 d0 = *(const float4*)&dotp[base];
    float4 d1 = *(const float4*)&dotp[base + 4];
    float dd[8] = {d0.x, d0.y, d0.z, d0.w, d1.x, d1.y, d1.z, d1.w};
    unsigned u[8];
    #pragma unroll
    for (int j = 0; j < 8; j++) {
        int r = base + j;
        float x = (r < NR) ? fmaxf(q2v + r2p[r] - 2.f * dd[j], 0.f) : FLT_MAX;
        u[j] = __float_as_uint(x);
    }

    int kk  = *kp;
    int kp1 = min(kk + 1, 64);

    for (int t = 0; t < kp1; t++) {
        unsigned a0 = min(u[0], u[1]), a1 = min(u[2], u[3]);
        unsigned a2 = min(u[4], u[5]), a3 = min(u[6], u[7]);
        unsigned lm = min(min(a0, a1), min(a2, a3));
        unsigned wm = __reduce_min_sync(0xffffffffu, lm);
        unsigned bal = __ballot_sync(0xffffffffu, lm == wm);
        bool leader = (lane == (__ffs(bal) - 1));
        int p = t & 1;
        if (lane == 0) wv[p][warp] = wm;
        __syncthreads();
        unsigned bm = wv[p][0]; int bw = 0;
        #pragma unroll
        for (int w = 1; w < 8; w++) {
            unsigned x = wv[p][w];
            if (x < bm) { bm = x; bw = w; }
        }
        if (tid == 0) topd[t] = __uint_as_float(bm);
        if (warp == bw && leader) {
            bool done = false;
            #pragma unroll
            for (int j = 0; j < 8; j++)
                if (!done && u[j] == wm) { u[j] = 0xFFFFFFFFu; done = true; }
        }
    }
    __syncthreads();

    if (warp == 0) {
        float dk = sqrtf(topd[kp1 - 1]);
        float s = 0.f;
        for (int i = lane; i < kp1; i += 32)
            if (i >= 1) s += logf(sqrtf(topd[i]) / dk);
        #pragma unroll
        for (int o = 16; o > 0; o >>= 1) s += __shfl_xor_sync(0xffffffffu, s, o);
        if (lane == 0) g_lid[b * 4 + l] = -(float)kk / s;
    }

    // fused final: last block computes the sigmoid head
    if (tid == 0) {
        __threadfence();
        unsigned t = atomicAdd(&g_ctr, 1u);
        slast = (t == (unsigned)(NB * 4 - 1));
    }
    __syncthreads();
    if (slast) {
        __threadfence();
        float z = rb[0];
        #pragma unroll
        for (int j = 0; j < 4; j++) z += g_lid[tid * 4 + j] * rw[j];
        outp[tid] = 1.f / (1.f + expf(-z));
        if (tid == 0) atomicExch(&g_ctr, 0u);
    }
}

// ---------------- launch (3 kernels) ----------------
extern "C" void kernel_launch(void* const* d_in, const int* in_sizes, int n_in,
                              void* d_out, int out_size)
{
    const float* feat[4] = {0, 0, 0, 0};
    const float* ref[4]  = {0, 0, 0, 0};
    const float* rw = 0;
    const float* rb = 0;
    const int*   kp = 0;
    int ones = 0;
    for (int i = 0; i < n_in; i++) {
        switch (in_sizes[i]) {
            case 51380224: feat[0] = (const float*)d_in[i]; break;
            case 25690112: feat[1] = (const float*)d_in[i]; break;
            case 12845056: feat[2] = (const float*)d_in[i]; break;
            case 6422528:  feat[3] = (const float*)d_in[i]; break;
            case 128000:   ref[0]  = (const float*)d_in[i]; break;
            case 256000:   ref[1]  = (const float*)d_in[i]; break;
            case 512000:   ref[2]  = (const float*)d_in[i]; break;
            case 1024000:  ref[3]  = (const float*)d_in[i]; break;
            case 4:        rw      = (const float*)d_in[i]; break;
            case 1:
                if (ones++ == 0) rb = (const float*)d_in[i];
                else             kp = (const int*)d_in[i];
                break;
            default: break;
        }
    }

    // 122688 warps / 8 per block = 15336 blocks
    pool_norm_kernel<<<15336, 256>>>(feat[0], feat[1], feat[2], feat[3],
                                     ref[0], ref[1], ref[2], ref[3]);

    dim3 gg(NRP / 64, NB / 128, 4);
    dim3 bt(16, 16);
    dist_gemm_kernel<<<gg, bt>>>(ref[0], ref[1], ref[2], ref[3]);

    dim3 gs(NB, 4);
    select_kernel<<<gs, 256>>>(kp, rw, rb, (float*)d_out);
}

// round 17
// speedup vs baseline: 1.3971x; 1.2220x over previous
#include <cuda_runtime.h>
#include <math.h>
#include <float.h>

// layers: C = {64,128,256,512}, HW = {3136,784,196,49}, B=256, R=2000
#define NB 256
#define NR 2000
#define NRP 2048

__constant__ int c_C[4]    = {64, 128, 256, 512};
__constant__ int c_qoff[4] = {0, 16384, 49152, 114688};

// scratch (static device globals; no allocation)
__device__ __align__(16) float g_fq[245760];        // pooled queries
__device__ __align__(16) float g_dot[4 * NB * NRP]; // q . ref^T, padded
__device__ float g_r2[4 * NR];
__device__ float g_lid[NB * 4];
__device__ unsigned g_ctr;                          // last-block ticket (reset each call)

// ---- tf32 mma helpers ----
__device__ __forceinline__ unsigned cvt_tf32(float x) {
    unsigned r;
    asm("cvt.rna.tf32.f32 %0, %1;" : "=r"(r) : "f"(x));
    return r;
}
__device__ __forceinline__ void mma_tf32(float* c,
    unsigned a0, unsigned a1, unsigned a2, unsigned a3,
    unsigned b0, unsigned b1)
{
    asm("mma.sync.aligned.m16n8k8.row.col.f32.tf32.tf32.f32 "
        "{%0,%1,%2,%3}, {%4,%5,%6,%7}, {%8,%9}, {%0,%1,%2,%3};"
        : "+f"(c[0]), "+f"(c[1]), "+f"(c[2]), "+f"(c[3])
        : "r"(a0), "r"(a1), "r"(a2), "r"(a3), "r"(b0), "r"(b1));
}

// ---------------- kernel 1: pooling (sub-warp rows) + ref norms (proven R16) ----------------
__global__ void __launch_bounds__(256) pool_norm_kernel(
    const float* __restrict__ f0, const float* __restrict__ f1,
    const float* __restrict__ f2, const float* __restrict__ f3,
    const float* __restrict__ r0, const float* __restrict__ r1,
    const float* __restrict__ r2, const float* __restrict__ r3)
{
    int gw   = (blockIdx.x * 256 + threadIdx.x) >> 5;
    int lane = threadIdx.x & 31;
    if (gw >= 122688) return;

    if (gw < 16384) {
        const float* src = f0 + (size_t)gw * 3136;
        const float4* s4 = (const float4*)src;
        float s = 0.f;
        #pragma unroll 4
        for (int i = lane; i < 784; i += 32) {
            float4 v = s4[i];
            s += (v.x + v.y) + (v.z + v.w);
        }
        #pragma unroll
        for (int o = 16; o > 0; o >>= 1) s += __shfl_xor_sync(0xffffffffu, s, o);
        if (lane == 0) g_fq[gw] = s / 3136.f;
    } else if (gw < 49152) {
        int row = gw - 16384;
        const float* src = f1 + (size_t)row * 784;
        const float4* s4 = (const float4*)src;
        float s = 0.f;
        #pragma unroll 4
        for (int i = lane; i < 196; i += 32) {
            float4 v = s4[i];
            s += (v.x + v.y) + (v.z + v.w);
        }
        #pragma unroll
        for (int o = 16; o > 0; o >>= 1) s += __shfl_xor_sync(0xffffffffu, s, o);
        if (lane == 0) g_fq[16384 + row] = s / 784.f;
    } else if (gw < 81920) {
        int base = (gw - 49152) * 2;
        int g    = lane >> 4;
        int sub  = lane & 15;
        int row  = base + g;
        const float4* s4 = (const float4*)(f2 + (size_t)row * 196);
        float s = 0.f;
        #pragma unroll 4
        for (int i = sub; i < 49; i += 16) {
            float4 v = s4[i];
            s += (v.x + v.y) + (v.z + v.w);
        }
        #pragma unroll
        for (int o = 8; o > 0; o >>= 1) s += __shfl_xor_sync(0xffffffffu, s, o);
        if (sub == 0) g_fq[49152 + row] = s / 196.f;
    } else if (gw < 114688) {
        int base = (gw - 81920) * 4;
        int g    = lane >> 3;
        int sub  = lane & 7;
        int row  = base + g;
        const float* src = f3 + (size_t)row * 49;
        float s = 0.f;
        #pragma unroll 7
        for (int i = sub; i < 49; i += 8) s += src[i];
        #pragma unroll
        for (int o = 4; o > 0; o >>= 1) s += __shfl_xor_sync(0xffffffffu, s, o);
        if (sub == 0) g_fq[114688 + row] = s / 49.f;
    } else {
        int idx = gw - 114688;
        int l = idx / NR, row = idx % NR;
        const float* rp = (l == 0) ? r0 : (l == 1) ? r1 : (l == 2) ? r2 : r3;
        int C = c_C[l];
        const float* src = rp + (size_t)row * C;
        float s = 0.f;
        const float4* s4 = (const float4*)src;
        int n4 = C >> 2;
        #pragma unroll 4
        for (int i = lane; i < n4; i += 32) {
            float4 v = s4[i];
            s += v.x * v.x + v.y * v.y + v.z * v.z + v.w * v.w;
        }
        #pragma unroll
        for (int o = 16; o > 0; o >>= 1) s += __shfl_xor_sync(0xffffffffu, s, o);
        if (lane == 0) g_r2[l * NR + row] = s;
    }
}

// ---------------- kernel 2: tf32 tensor-core distance GEMM, 64x64 tile ----------------
// warp layout: 8 warps; warpM = warp&3 (16 rows each), warpN = warp>>2 (32 cols each, 4 n8-tiles)
__global__ void __launch_bounds__(256) dist_gemm_kernel(
    const float* __restrict__ r0, const float* __restrict__ r1,
    const float* __restrict__ r2, const float* __restrict__ r3)
{
    int l = 3 - blockIdx.z;     // heavy layers first
    int C = c_C[l];
    const float* ref = (l == 0) ? r0 : (l == 1) ? r1 : (l == 2) ? r2 : r3;
    const float* q   = g_fq + c_qoff[l];

    int bt = blockIdx.y << 6;   // batch tile (64)
    int rt = blockIdx.x << 6;   // ref tile (64)

    __shared__ float qs[64][36];   // [row][k], pitch 36 keeps 16B align + spread banks
    __shared__ float rs[64][36];

    int tid  = threadIdx.x;
    int warp = tid >> 5;
    int lane = tid & 31;
    int wm  = (warp & 3) * 16;
    int wn  = (warp >> 2) * 32;
    int gid = lane >> 2;   // 0..7
    int tig = lane & 3;    // 0..3

    float acc[4][4];
    #pragma unroll
    for (int i = 0; i < 4; i++)
        #pragma unroll
        for (int j = 0; j < 4; j++) acc[i][j] = 0.f;

    int nch = C >> 5;   // k-chunks of 32
    for (int ch = 0; ch < nch; ch++) {
        __syncthreads();
        int k0 = ch * 32;
        // load 64x32 q tile + 64x32 r tile (2 float4 per thread per tile)
        #pragma unroll
        for (int i = 0; i < 2; i++) {
            int idx = tid + i * 256;
            int row = idx >> 3, c4 = idx & 7;
            *(float4*)&qs[row][c4 * 4] =
                *(const float4*)&q[(size_t)(bt + row) * C + k0 + c4 * 4];
            int rr = rt + row;
            float4 rv = make_float4(0.f, 0.f, 0.f, 0.f);
            if (rr < NR) rv = *(const float4*)&ref[(size_t)rr * C + k0 + c4 * 4];
            *(float4*)&rs[row][c4 * 4] = rv;
        }
        __syncthreads();

        #pragma unroll
        for (int ks = 0; ks < 4; ks++) {
            int kb = ks * 8;
            unsigned a0 = cvt_tf32(qs[wm + gid][kb + tig]);
            unsigned a1 = cvt_tf32(qs[wm + gid + 8][kb + tig]);
            unsigned a2 = cvt_tf32(qs[wm + gid][kb + tig + 4]);
            unsigned a3 = cvt_tf32(qs[wm + gid + 8][kb + tig + 4]);
            #pragma unroll
            for (int nt = 0; nt < 4; nt++) {
                int nb = wn + nt * 8 + gid;
                unsigned b0 = cvt_tf32(rs[nb][kb + tig]);
                unsigned b1 = cvt_tf32(rs[nb][kb + tig + 4]);
                mma_tf32(acc[nt], a0, a1, a2, a3, b0, b1);
            }
        }
    }

    float* out = g_dot + ((size_t)l * NB + bt) * NRP + rt;
    #pragma unroll
    for (int nt = 0; nt < 4; nt++) {
        int col = wn + nt * 8 + 2 * tig;
        *(float2*)&out[(size_t)(wm + gid) * NRP + col] =
            make_float2(acc[nt][0], acc[nt][1]);
        *(float2*)&out[(size_t)(wm + gid + 8) * NRP + col] =
            make_float2(acc[nt][2], acc[nt][3]);
    }
}

// ---------------- kernel 3: R8 extraction select + inline q2 + fused final (proven) ----------------
__global__ void __launch_bounds__(256) select_kernel(
    const int* __restrict__ kp, const float* __restrict__ rw,
    const float* __restrict__ rb, float* __restrict__ outp)
{
    int b = blockIdx.x;
    int l = blockIdx.y;
    int tid  = threadIdx.x;
    int warp = tid >> 5;
    int lane = tid & 31;

    __shared__ unsigned wv[2][8];
    __shared__ float wq[8];
    __shared__ float topd[64];
    __shared__ int slast;

    int C = c_C[l];
    const float* dotp = g_dot + ((size_t)l * NB + b) * NRP;
    const float* r2p  = g_r2 + l * NR;

    // inline q2 = ||fq[b]||^2
    const float* qrow = g_fq + c_qoff[l] + (size_t)b * C;
    float sq = 0.f;
    int n4 = C >> 2;
    if (tid < n4) {
        float4 v = ((const float4*)qrow)[tid];
        sq = v.x * v.x + v.y * v.y + v.z * v.z + v.w * v.w;
    }
    #pragma unroll
    for (int o = 16; o > 0; o >>= 1) sq += __shfl_xor_sync(0xffffffffu, sq, o);
    if (lane == 0) wq[warp] = sq;
    __syncthreads();
    float q2v = wq[0] + wq[1] + wq[2] + wq[3] + wq[4] + wq[5] + wq[6] + wq[7];

    int base = tid * 8;
    float4 d0 = *(const float4*)&dotp[base];
    float4 d1 = *(const float4*)&dotp[base + 4];
    float dd[8] = {d0.x, d0.y, d0.z, d0.w, d1.x, d1.y, d1.z, d1.w};
    unsigned u[8];
    #pragma unroll
    for (int j = 0; j < 8; j++) {
        int r = base + j;
        float x = (r < NR) ? fmaxf(q2v + r2p[r] - 2.f * dd[j], 0.f) : FLT_MAX;
        u[j] = __float_as_uint(x);
    }

    int kk  = *kp;
    int kp1 = min(kk + 1, 64);

    for (int t = 0; t < kp1; t++) {
        unsigned a0 = min(u[0], u[1]), a1 = min(u[2], u[3]);
        unsigned a2 = min(u[4], u[5]), a3 = min(u[6], u[7]);
        unsigned lm = min(min(a0, a1), min(a2, a3));
        unsigned wm = __reduce_min_sync(0xffffffffu, lm);
        unsigned bal = __ballot_sync(0xffffffffu, lm == wm);
        bool leader = (lane == (__ffs(bal) - 1));
        int p = t & 1;
        if (lane == 0) wv[p][warp] = wm;
        __syncthreads();
        unsigned bm = wv[p][0]; int bw = 0;
        #pragma unroll
        for (int w = 1; w < 8; w++) {
            unsigned x = wv[p][w];
            if (x < bm) { bm = x; bw = w; }
        }
        if (tid == 0) topd[t] = __uint_as_float(bm);
        if (warp == bw && leader) {
            bool done = false;
            #pragma unroll
            for (int j = 0; j < 8; j++)
                if (!done && u[j] == wm) { u[j] = 0xFFFFFFFFu; done = true; }
        }
    }
    __syncthreads();

    if (warp == 0) {
        float dk = sqrtf(topd[kp1 - 1]);
        float s = 0.f;
        for (int i = lane; i < kp1; i += 32)
            if (i >= 1) s += logf(sqrtf(topd[i]) / dk);
        #pragma unroll
        for (int o = 16; o > 0; o >>= 1) s += __shfl_xor_sync(0xffffffffu, s, o);
        if (lane == 0) g_lid[b * 4 + l] = -(float)kk / s;
    }

    // fused final: last block computes the sigmoid head
    if (tid == 0) {
        __threadfence();
        unsigned t = atomicAdd(&g_ctr, 1u);
        slast = (t == (unsigned)(NB * 4 - 1));
    }
    __syncthreads();
    if (slast) {
        __threadfence();
        float z = rb[0];
        #pragma unroll
        for (int j = 0; j < 4; j++) z += g_lid[tid * 4 + j] * rw[j];
        outp[tid] = 1.f / (1.f + expf(-z));
        if (tid == 0) atomicExch(&g_ctr, 0u);
    }
}

// ---------------- launch (3 kernels) ----------------
extern "C" void kernel_launch(void* const* d_in, const int* in_sizes, int n_in,
                              void* d_out, int out_size)
{
    const float* feat[4] = {0, 0, 0, 0};
    const float* ref[4]  = {0, 0, 0, 0};
    const float* rw = 0;
    const float* rb = 0;
    const int*   kp = 0;
    int ones = 0;
    for (int i = 0; i < n_in; i++) {
        switch (in_sizes[i]) {
            case 51380224: feat[0] = (const float*)d_in[i]; break;
            case 25690112: feat[1] = (const float*)d_in[i]; break;
            case 12845056: feat[2] = (const float*)d_in[i]; break;
            case 6422528:  feat[3] = (const float*)d_in[i]; break;
            case 128000:   ref[0]  = (const float*)d_in[i]; break;
            case 256000:   ref[1]  = (const float*)d_in[i]; break;
            case 512000:   ref[2]  = (const float*)d_in[i]; break;
            case 1024000:  ref[3]  = (const float*)d_in[i]; break;
            case 4:        rw      = (const float*)d_in[i]; break;
            case 1:
                if (ones++ == 0) rb = (const float*)d_in[i];
                else             kp = (const int*)d_in[i];
                break;
            default: break;
        }
    }

    pool_norm_kernel<<<15336, 256>>>(feat[0], feat[1], feat[2], feat[3],
                                     ref[0], ref[1], ref[2], ref[3]);

    dim3 gg(NRP / 64, NB / 64, 4);   // (32, 4, 4) = 512 blocks; z reversed inside
    dist_gemm_kernel<<<gg, 256>>>(ref[0], ref[1], ref[2], ref[3]);

    dim3 gs(NB, 4);
    select_kernel<<<gs, 256>>>(kp, rw, rb, (float*)d_out);
}